// round 1
// baseline (speedup 1.0000x reference)
#include <cuda_runtime.h>
#include <cstdint>

// ---------------------------------------------------------------------------
// DilatedReparamBlock fused: merge 7 BN(dwconv) branches into one 13x13
// depthwise conv + bias, then run a single packed-fp32 (fma.rn.f32x2) conv.
// x: [16, 384, 56, 56] fp32 -> out same shape.
// ---------------------------------------------------------------------------

#define C_CH 384
#define NB 16
#define HW 56
#define PAD 6
#define PH 68                 // 56 + 2*6 padded tile
#define IMG_PER_BLK 4
#define THREADS 224           // 4 images * 56 threads (7 x-tiles * 8 y-threads)
#define SMEM_BYTES (IMG_PER_BLK * PH * PH * 4)

// Merged weights: per channel, 13 rows, each row padded to 14 float2 entries.
// Each entry is the tap value DUPLICATED (w,w) so it is a ready FFMA2 operand.
__device__ float2 g_Wd[C_CH * 13 * 14];
__device__ float  g_bias[C_CH];

// ---------------------------------------------------------------------------
// Kernel 1: merge weights + BN into 13x13 kernel and bias (trivial cost)
// ---------------------------------------------------------------------------
__global__ void merge_kernel(const float* __restrict__ w_lk,
                             const float* __restrict__ w_b0,
                             const float* __restrict__ w_b1,
                             const float* __restrict__ w_b2,
                             const float* __restrict__ w_b3,
                             const float* __restrict__ w_b4,
                             const float* __restrict__ w_b5,
                             const float* __restrict__ gamma,
                             const float* __restrict__ beta,
                             const float* __restrict__ mean,
                             const float* __restrict__ var) {
    int c = blockIdx.x;
    int t = threadIdx.x;

    float inv[7];
#pragma unroll
    for (int m = 0; m < 7; m++)
        inv[m] = gamma[m * C_CH + c] * rsqrtf(var[m * C_CH + c] + 1e-5f);

    if (t < 169) {
        int i = t / 13, j = t % 13;
        float val = inv[0] * w_lk[c * 169 + t];

        const float* ws[6] = {w_b0, w_b1, w_b2, w_b3, w_b4, w_b5};
        const int ks[6] = {5, 7, 7, 3, 3, 3};
        const int rs[6] = {1, 1, 2, 3, 4, 5};
#pragma unroll
        for (int b = 0; b < 6; b++) {
            int k = ks[b], r = rs[b];
            int span = r * (k - 1) + 1;
            int off = (13 - span) / 2;           // center the dilated kernel
            int ai = i - off, aj = j - off;
            if (ai >= 0 && aj >= 0 && (ai % r) == 0 && (aj % r) == 0) {
                int a = ai / r, bb = aj / r;
                if (a < k && bb < k)
                    val += inv[b + 1] * ws[b][c * k * k + a * k + bb];
            }
        }
        g_Wd[(c * 13 + i) * 14 + j] = make_float2(val, val);
    }
    if (t == 0) {
        float bsum = 0.f;
#pragma unroll
        for (int m = 0; m < 7; m++)
            bsum += beta[m * C_CH + c] - mean[m * C_CH + c] * inv[m];
        g_bias[c] = bsum;
    }
}

// ---------------------------------------------------------------------------
// Packed fp32 helpers (sm_103a FFMA2 path — PTX-only, ptxas won't auto-fuse)
// ---------------------------------------------------------------------------
__device__ __forceinline__ unsigned long long pk2(float lo, float hi) {
    unsigned long long r;
    asm("mov.b64 %0, {%1,%2};" : "=l"(r) : "f"(lo), "f"(hi));
    return r;
}
__device__ __forceinline__ void fma2(unsigned long long& a,
                                     unsigned long long x,
                                     unsigned long long w) {
    asm("fma.rn.f32x2 %0, %1, %2, %0;" : "+l"(a) : "l"(x), "l"(w));
}

// ---------------------------------------------------------------------------
// Kernel 2: depthwise 13x13 conv + bias.
// Block = 4 (n,c) images. Per image: 56 threads = 7 x-tiles (8 wide) x 8 ty.
// Each thread computes an 8-wide x 7-row strip via 4 packed accumulators/row.
// Input staged zero-padded 68x68 in smem -> branch-free hot loop.
// ---------------------------------------------------------------------------
extern __shared__ float s_in[];

__global__ __launch_bounds__(THREADS)
void conv13_kernel(const float* __restrict__ x, float* __restrict__ out) {
    int t = threadIdx.x;
    int img_l = t / 56;
    int s = t % 56;
    int tx = s % 7, ty = s / 7;
    int x0 = tx * 8;
    int y0 = ty * 7;

    int img = blockIdx.x * IMG_PER_BLK + img_l;   // flat (n*C + c)
    int c = img % C_CH;

    float* my = s_in + img_l * (PH * PH);
    const float* gx = x + (size_t)img * (HW * HW);

    // Stage zero-padded tile (coalesced rows; 56 threads per image)
    for (int pos = s; pos < PH * PH; pos += 56) {
        int r = pos / PH, cc = pos % PH;
        int rr = r - PAD, cg = cc - PAD;
        float v = 0.f;
        if (rr >= 0 && rr < HW && cg >= 0 && cg < HW)
            v = __ldg(gx + rr * HW + cg);
        my[pos] = v;
    }
    __syncthreads();

    float bb = __ldg(&g_bias[c]);
    unsigned long long bias2 = pk2(bb, bb);

    const ulonglong2* wbase =
        reinterpret_cast<const ulonglong2*>(g_Wd) + (size_t)c * 13 * 7;
    float* obase = out + (size_t)img * (HW * HW);

    for (int oy = 0; oy < 7; oy++) {
        unsigned long long a0 = bias2, a1 = bias2, a2 = bias2, a3 = bias2;
        const float* rbase0 = my + (y0 + oy) * PH + x0;  // padded coords

#pragma unroll
        for (int i = 0; i < 13; i++) {
            const float2* rp = reinterpret_cast<const float2*>(rbase0 + i * PH);
            float2 f[10];
#pragma unroll
            for (int k = 0; k < 10; k++) f[k] = rp[k];     // 10x LDS.64

            ulonglong2 wv[7];
#pragma unroll
            for (int m = 0; m < 7; m++) wv[m] = __ldg(wbase + i * 7 + m);

            // packed input pairs p[m] = (in[m], in[m+1]), m = 0..18
            unsigned long long p[19];
#pragma unroll
            for (int k = 0; k < 10; k++) p[2 * k] = pk2(f[k].x, f[k].y);
#pragma unroll
            for (int k = 0; k < 9; k++) p[2 * k + 1] = pk2(f[k].y, f[k + 1].x);

#pragma unroll
            for (int j = 0; j < 13; j++) {
                unsigned long long w = (j & 1) ? wv[j >> 1].y : wv[j >> 1].x;
                fma2(a0, p[j],     w);
                fma2(a1, p[j + 2], w);
                fma2(a2, p[j + 4], w);
                fma2(a3, p[j + 6], w);
            }
        }

        unsigned long long* orow = reinterpret_cast<unsigned long long*>(
            obase + (y0 + oy) * HW + x0);
        orow[0] = a0;
        orow[1] = a1;
        orow[2] = a2;
        orow[3] = a3;
    }
}

// ---------------------------------------------------------------------------
extern "C" void kernel_launch(void* const* d_in, const int* in_sizes, int n_in,
                              void* d_out, int out_size) {
    const float* x    = (const float*)d_in[0];
    const float* w_lk = (const float*)d_in[1];
    const float* w_b0 = (const float*)d_in[2];
    const float* w_b1 = (const float*)d_in[3];
    const float* w_b2 = (const float*)d_in[4];
    const float* w_b3 = (const float*)d_in[5];
    const float* w_b4 = (const float*)d_in[6];
    const float* w_b5 = (const float*)d_in[7];
    const float* gam  = (const float*)d_in[8];
    const float* bet  = (const float*)d_in[9];
    const float* mea  = (const float*)d_in[10];
    const float* var  = (const float*)d_in[11];
    float* out = (float*)d_out;

    merge_kernel<<<C_CH, 192>>>(w_lk, w_b0, w_b1, w_b2, w_b3, w_b4, w_b5,
                                gam, bet, mea, var);

    cudaFuncSetAttribute(conv13_kernel,
                         cudaFuncAttributeMaxDynamicSharedMemorySize,
                         SMEM_BYTES);
    int grid = (NB * C_CH) / IMG_PER_BLK;  // 1536
    conv13_kernel<<<grid, THREADS, SMEM_BYTES>>>(x, out);
}

// round 3
// speedup vs baseline: 1.1011x; 1.1011x over previous
#include <cuda_runtime.h>
#include <cstdint>

// ---------------------------------------------------------------------------
// DilatedReparamBlock fused: merge 7 BN(dwconv) branches into one 13x13
// depthwise conv + bias (exact reparam), then run a single packed-fp32
// (fma.rn.f32x2 / FFMA2) conv with input-row-outer register accumulation.
// x: [16, 384, 56, 56] fp32 -> out same shape.
// ---------------------------------------------------------------------------

#define C_CH 384
#define NB 16
#define HW 56
#define PAD 6
#define PH 68                  // 56 + 2*6 padded tile
#define IMG_PER_BLK 4
#define THREADS 224            // 4 images * 56 threads (7 x-tiles * 8 y-tiles)
#define WSTRIDE 16             // u64 (dup-weight taps) per weight row (128B)
#define W_U64_PER_IMG (13 * WSTRIDE)                   // 208
#define SMEM_IN_BYTES (IMG_PER_BLK * PH * PH * 4)      // 73984
#define SMEM_W_BYTES  (IMG_PER_BLK * W_U64_PER_IMG * 8)// 6656
#define SMEM_BYTES    (SMEM_IN_BYTES + SMEM_W_BYTES)   // 80640

// Merged weights: per channel, 13 rows x WSTRIDE u64; entry j (j<13) is the
// tap value DUPLICATED (w,w) so it is a ready FFMA2 b-operand.
__device__ unsigned long long g_Wd[C_CH * W_U64_PER_IMG];
__device__ float g_bias[C_CH];

// ---------------------------------------------------------------------------
// Kernel 1: fold the 7 BN(dwconv) branches into one 13x13 kernel + bias.
// ---------------------------------------------------------------------------
__global__ void merge_kernel(const float* __restrict__ w_lk,
                             const float* __restrict__ w_b0,
                             const float* __restrict__ w_b1,
                             const float* __restrict__ w_b2,
                             const float* __restrict__ w_b3,
                             const float* __restrict__ w_b4,
                             const float* __restrict__ w_b5,
                             const float* __restrict__ gamma,
                             const float* __restrict__ beta,
                             const float* __restrict__ mean,
                             const float* __restrict__ var) {
    int c = blockIdx.x;
    int t = threadIdx.x;

    float inv[7];
#pragma unroll
    for (int m = 0; m < 7; m++)
        inv[m] = gamma[m * C_CH + c] * rsqrtf(var[m * C_CH + c] + 1e-5f);

    if (t < 169) {
        int i = t / 13, j = t % 13;
        float val = inv[0] * w_lk[c * 169 + t];

        const float* ws[6] = {w_b0, w_b1, w_b2, w_b3, w_b4, w_b5};
        const int ks[6] = {5, 7, 7, 3, 3, 3};
        const int rs[6] = {1, 1, 2, 3, 4, 5};
#pragma unroll
        for (int b = 0; b < 6; b++) {
            int k = ks[b], r = rs[b];
            int span = r * (k - 1) + 1;
            int off = (13 - span) / 2;           // center the dilated kernel
            int ai = i - off, aj = j - off;
            if (ai >= 0 && aj >= 0 && (ai % r) == 0 && (aj % r) == 0) {
                int a = ai / r, bb = aj / r;
                if (a < k && bb < k)
                    val += inv[b + 1] * ws[b][c * k * k + a * k + bb];
            }
        }
        float2 d2 = make_float2(val, val);
        g_Wd[c * W_U64_PER_IMG + i * WSTRIDE + j] =
            *reinterpret_cast<unsigned long long*>(&d2);
    }
    if (t == 0) {
        float bsum = 0.f;
#pragma unroll
        for (int m = 0; m < 7; m++)
            bsum += beta[m * C_CH + c] - mean[m * C_CH + c] * inv[m];
        g_bias[c] = bsum;
    }
}

// ---------------------------------------------------------------------------
// Packed fp32 helpers (FFMA2 — PTX-only on sm_103a)
// ---------------------------------------------------------------------------
__device__ __forceinline__ unsigned long long pk2(float lo, float hi) {
    unsigned long long r;
    asm("mov.b64 %0, {%1,%2};" : "=l"(r) : "f"(lo), "f"(hi));
    return r;
}
__device__ __forceinline__ void fma2(unsigned long long& a,
                                     unsigned long long x,
                                     unsigned long long w) {
    asm("fma.rn.f32x2 %0, %1, %2, %0;" : "+l"(a) : "l"(x), "l"(w));
}

// ---------------------------------------------------------------------------
// Kernel 2: depthwise 13x13 conv + bias, input-row-outer.
// Block = 4 (n,c) images. Per image: 56 threads = 7 x-tiles (8 wide) x 8 ty.
// Each thread owns a 8-wide x 7-row output strip: 7x4 packed accumulators
// stay in registers; the 19 contributing input rows are each loaded and
// packed exactly ONCE, then fanned out to the output rows they touch.
// ---------------------------------------------------------------------------
extern __shared__ char s_raw[];

__global__ __launch_bounds__(THREADS, 2)
void conv13_kernel(const float* __restrict__ x, float* __restrict__ out) {
    float* s_in = reinterpret_cast<float*>(s_raw);
    unsigned long long* s_w =
        reinterpret_cast<unsigned long long*>(s_raw + SMEM_IN_BYTES);

    int t = threadIdx.x;
    int img_l = t / 56;
    int s = t % 56;
    int tx = s % 7, ty = s / 7;
    int x0 = tx * 8;
    int y0 = ty * 7;

    int img = blockIdx.x * IMG_PER_BLK + img_l;   // flat (n*C + c)
    int c = img % C_CH;

    float* my = s_in + img_l * (PH * PH);
    unsigned long long* mw = s_w + img_l * W_U64_PER_IMG;
    const float* gx = x + (size_t)img * (HW * HW);

    // Stage merged weights into smem: 208 u64 = 104 ulonglong2 per image.
    // Guarded stride loop (56 threads -> iterations at k, k+56; k<104).
    {
        const ulonglong2* src =
            reinterpret_cast<const ulonglong2*>(g_Wd + (size_t)c * W_U64_PER_IMG);
        ulonglong2* dst = reinterpret_cast<ulonglong2*>(mw);
        for (int k = s; k < W_U64_PER_IMG / 2; k += 56)
            dst[k] = __ldg(src + k);
    }

    // Stage zero-padded input tile (56 threads per image)
    for (int pos = s; pos < PH * PH; pos += 56) {
        int r = pos / PH, cc = pos % PH;
        int rr = r - PAD, cg = cc - PAD;
        float v = 0.f;
        if (rr >= 0 && rr < HW && cg >= 0 && cg < HW)
            v = __ldg(gx + rr * HW + cg);
        my[pos] = v;
    }
    __syncthreads();

    float bb = __ldg(&g_bias[c]);
    unsigned long long bias2 = pk2(bb, bb);

    unsigned long long acc[7][4];
#pragma unroll
    for (int d = 0; d < 7; d++)
#pragma unroll
        for (int q = 0; q < 4; q++) acc[d][q] = bias2;

    const float* rbase = my + y0 * PH + x0;   // padded coords

#pragma unroll 1
    for (int ir = 0; ir < 19; ir++) {
        // Load + pack this input row once: 10 LDS.64, 9 misaligned repacks
        const float2* rp = reinterpret_cast<const float2*>(rbase + ir * PH);
        float2 f[10];
#pragma unroll
        for (int k = 0; k < 10; k++) f[k] = rp[k];

        unsigned long long p[19];
#pragma unroll
        for (int k = 0; k < 10; k++) p[2 * k] = pk2(f[k].x, f[k].y);
#pragma unroll
        for (int k = 0; k < 9; k++) p[2 * k + 1] = pk2(f[k].y, f[k + 1].x);

        // Fan out to the output rows this input row contributes to.
        // Output row d uses input rows ir = d..d+12 with weight row ir-d.
#pragma unroll
        for (int d = 0; d < 7; d++) {
            if (d <= ir && ir - d <= 12) {
                const unsigned long long* wr = mw + (ir - d) * WSTRIDE;
#pragma unroll
                for (int j = 0; j < 13; j++) {
                    unsigned long long w = wr[j];     // broadcast LDS.64
                    fma2(acc[d][0], p[j],     w);
                    fma2(acc[d][1], p[j + 2], w);
                    fma2(acc[d][2], p[j + 4], w);
                    fma2(acc[d][3], p[j + 6], w);
                }
            }
        }
    }

    float* obase = out + (size_t)img * (HW * HW);
#pragma unroll
    for (int d = 0; d < 7; d++) {
        unsigned long long* orow = reinterpret_cast<unsigned long long*>(
            obase + (y0 + d) * HW + x0);
#pragma unroll
        for (int q = 0; q < 4; q++) orow[q] = acc[d][q];
    }
}

// ---------------------------------------------------------------------------
extern "C" void kernel_launch(void* const* d_in, const int* in_sizes, int n_in,
                              void* d_out, int out_size) {
    const float* x    = (const float*)d_in[0];
    const float* w_lk = (const float*)d_in[1];
    const float* w_b0 = (const float*)d_in[2];
    const float* w_b1 = (const float*)d_in[3];
    const float* w_b2 = (const float*)d_in[4];
    const float* w_b3 = (const float*)d_in[5];
    const float* w_b4 = (const float*)d_in[6];
    const float* w_b5 = (const float*)d_in[7];
    const float* gam  = (const float*)d_in[8];
    const float* bet  = (const float*)d_in[9];
    const float* mea  = (const float*)d_in[10];
    const float* var  = (const float*)d_in[11];
    float* out = (float*)d_out;

    merge_kernel<<<C_CH, 192>>>(w_lk, w_b0, w_b1, w_b2, w_b3, w_b4, w_b5,
                                gam, bet, mea, var);

    cudaFuncSetAttribute(conv13_kernel,
                         cudaFuncAttributeMaxDynamicSharedMemorySize,
                         SMEM_BYTES);
    int grid = (NB * C_CH) / IMG_PER_BLK;  // 1536
    conv13_kernel<<<grid, THREADS, SMEM_BYTES>>>(x, out);
}